// round 13
// baseline (speedup 1.0000x reference)
#include <cuda_runtime.h>
#include <stdint.h>

// Problem dims
#define T_STEPS 100
#define BATCH   512
#define NI      784
#define NH      1024
#define NO      10
#define M_TOT   (T_STEPS * BATCH)   // 51200
#define NIT     49                   // K chunks of 16

// Scratch (static __device__ arrays: allocation-free per harness rules)
__device__ float          g_cur1[(size_t)M_TOT * NH];   // ~210 MB
__device__ unsigned char  g_spk1[(size_t)M_TOT * NH];   // ~52 MB
__device__ float          g_cur2[(size_t)M_TOT * NO];   // ~2 MB

// ---------------------------------------------------------------------------
// Kernel A: cur1[m,n] = sum_k X[m,k]*W1[n,k] + b1[n]
// R11-proven config: 128x128x16 SGEMM, 256 thr, 8x8 microtile, smem
// double-buffered (one __syncthreads per K-iter), plain fragment loads
// (ptxas pipelines them). Accumulation order identical to round 1 ->
// bit-identical cur1.
// ---------------------------------------------------------------------------
__global__ __launch_bounds__(256, 2) void k_gemm1(const float* __restrict__ X,
                                                  const float* __restrict__ W1,
                                                  const float* __restrict__ bias) {
    __shared__ __align__(16) float As[2][16][128];
    __shared__ __align__(16) float Bs[2][16][128];
    const int K = NI;       // 784 = 49 * 16
    const int N = NH;       // 1024

    int tid = threadIdx.x;
    int bn  = blockIdx.x;   // 0..7
    int bm  = blockIdx.y;   // 0..399

    int lrow = tid >> 1;          // 0..127
    int lcol = (tid & 1) << 3;    // 0 or 8

    const float* aptr = X  + (size_t)(bm * 128 + lrow) * K + lcol;
    const float* bptr = W1 + (size_t)(bn * 128 + lrow) * K + lcol;

    int ty = tid >> 4;   // 0..15
    int tx = tid & 15;   // 0..15

    float acc[8][8];
#pragma unroll
    for (int i = 0; i < 8; i++)
#pragma unroll
        for (int j = 0; j < 8; j++) acc[i][j] = 0.0f;

    float4 a0, a1, b0, b1;

    // ---- prologue: tile 0 -> regs -> buf 0 ----
    a0 = *(const float4*)(aptr);
    a1 = *(const float4*)(aptr + 4);
    b0 = *(const float4*)(bptr);
    b1 = *(const float4*)(bptr + 4);
    As[0][lcol + 0][lrow] = a0.x; As[0][lcol + 1][lrow] = a0.y;
    As[0][lcol + 2][lrow] = a0.z; As[0][lcol + 3][lrow] = a0.w;
    As[0][lcol + 4][lrow] = a1.x; As[0][lcol + 5][lrow] = a1.y;
    As[0][lcol + 6][lrow] = a1.z; As[0][lcol + 7][lrow] = a1.w;
    Bs[0][lcol + 0][lrow] = b0.x; Bs[0][lcol + 1][lrow] = b0.y;
    Bs[0][lcol + 2][lrow] = b0.z; Bs[0][lcol + 3][lrow] = b0.w;
    Bs[0][lcol + 4][lrow] = b1.x; Bs[0][lcol + 5][lrow] = b1.y;
    Bs[0][lcol + 6][lrow] = b1.z; Bs[0][lcol + 7][lrow] = b1.w;
    // prefetch tile 1 into regs
    a0 = *(const float4*)(aptr + 16);
    a1 = *(const float4*)(aptr + 20);
    b0 = *(const float4*)(bptr + 16);
    b1 = *(const float4*)(bptr + 20);
    __syncthreads();

    for (int it = 0; it < NIT; it++) {
        const int buf = it & 1;
        const int nbuf = buf ^ 1;

        // ---- STS tile(it+1) into the other buffer ----
        if (it + 1 < NIT) {
            As[nbuf][lcol + 0][lrow] = a0.x; As[nbuf][lcol + 1][lrow] = a0.y;
            As[nbuf][lcol + 2][lrow] = a0.z; As[nbuf][lcol + 3][lrow] = a0.w;
            As[nbuf][lcol + 4][lrow] = a1.x; As[nbuf][lcol + 5][lrow] = a1.y;
            As[nbuf][lcol + 6][lrow] = a1.z; As[nbuf][lcol + 7][lrow] = a1.w;
            Bs[nbuf][lcol + 0][lrow] = b0.x; Bs[nbuf][lcol + 1][lrow] = b0.y;
            Bs[nbuf][lcol + 2][lrow] = b0.z; Bs[nbuf][lcol + 3][lrow] = b0.w;
            Bs[nbuf][lcol + 4][lrow] = b1.x; Bs[nbuf][lcol + 5][lrow] = b1.y;
            Bs[nbuf][lcol + 6][lrow] = b1.z; Bs[nbuf][lcol + 7][lrow] = b1.w;
        }
        // ---- LDG prefetch tile(it+2) (latency hidden under compute) ----
        if (it + 2 < NIT) {
            const int kf = (it + 2) * 16;
            a0 = *(const float4*)(aptr + kf);
            a1 = *(const float4*)(aptr + kf + 4);
            b0 = *(const float4*)(bptr + kf);
            b1 = *(const float4*)(bptr + kf + 4);
        }

        // ---- compute from current buffer (identical order to round 1) ----
#pragma unroll
        for (int kk = 0; kk < 16; kk++) {
            float4 aA = *(const float4*)&As[buf][kk][ty * 4];
            float4 aB = *(const float4*)&As[buf][kk][ty * 4 + 64];
            float4 bA = *(const float4*)&Bs[buf][kk][tx * 4];
            float4 bB = *(const float4*)&Bs[buf][kk][tx * 4 + 64];
            float av[8] = {aA.x, aA.y, aA.z, aA.w, aB.x, aB.y, aB.z, aB.w};
            float bv[8] = {bA.x, bA.y, bA.z, bA.w, bB.x, bB.y, bB.z, bB.w};
#pragma unroll
            for (int i = 0; i < 8; i++)
#pragma unroll
                for (int j = 0; j < 8; j++)
                    acc[i][j] += av[i] * bv[j];
        }
        __syncthreads();
    }

    // Epilogue
    int crow0 = bm * 128 + ty * 4;
    int ccol0 = bn * 128 + tx * 4;
    float4 bs0 = *(const float4*)(bias + ccol0);
    float4 bs1 = *(const float4*)(bias + ccol0 + 64);

#pragma unroll
    for (int i = 0; i < 4; i++) {
        float* c0 = g_cur1 + (size_t)(crow0 + i) * N + ccol0;
        float4 v;
        v.x = acc[i][0] + bs0.x; v.y = acc[i][1] + bs0.y;
        v.z = acc[i][2] + bs0.z; v.w = acc[i][3] + bs0.w;
        *(float4*)(c0) = v;
        v.x = acc[i][4] + bs1.x; v.y = acc[i][5] + bs1.y;
        v.z = acc[i][6] + bs1.z; v.w = acc[i][7] + bs1.w;
        *(float4*)(c0 + 64) = v;

        float* c1 = g_cur1 + (size_t)(crow0 + 64 + i) * N + ccol0;
        v.x = acc[4 + i][0] + bs0.x; v.y = acc[4 + i][1] + bs0.y;
        v.z = acc[4 + i][2] + bs0.z; v.w = acc[4 + i][3] + bs0.w;
        *(float4*)(c1) = v;
        v.x = acc[4 + i][4] + bs1.x; v.y = acc[4 + i][5] + bs1.y;
        v.z = acc[4 + i][6] + bs1.z; v.w = acc[4 + i][7] + bs1.w;
        *(float4*)(c1 + 64) = v;
    }
}

// ---------------------------------------------------------------------------
// Kernel B: layer-1 leaky scan, 4 neurons per thread (float4/uchar4).
// (R11-proven config.)
// ---------------------------------------------------------------------------
__global__ __launch_bounds__(256) void k_scan1() {
    int i4 = blockIdx.x * blockDim.x + threadIdx.x;   // 0 .. B*NH/4-1
    const size_t stride = (size_t)BATCH * NH;
    float m0 = 0.0f, m1 = 0.0f, m2 = 0.0f, m3 = 0.0f;
    for (int t = 0; t < T_STEPS; t++) {
        float4 c = *(const float4*)(g_cur1 + (size_t)t * stride + (size_t)i4 * 4);
        m0 = 0.9f * m0 + c.x - ((m0 > 1.0f) ? 1.0f : 0.0f);
        m1 = 0.9f * m1 + c.y - ((m1 > 1.0f) ? 1.0f : 0.0f);
        m2 = 0.9f * m2 + c.z - ((m2 > 1.0f) ? 1.0f : 0.0f);
        m3 = 0.9f * m3 + c.w - ((m3 > 1.0f) ? 1.0f : 0.0f);
        uchar4 s;
        s.x = (m0 > 1.0f) ? 1 : 0;
        s.y = (m1 > 1.0f) ? 1 : 0;
        s.z = (m2 > 1.0f) ? 1 : 0;
        s.w = (m3 > 1.0f) ? 1 : 0;
        *(uchar4*)(g_spk1 + (size_t)t * stride + (size_t)i4 * 4) = s;
    }
}

// ---------------------------------------------------------------------------
// Kernel C: cur2[tb,j] = sum_n spk1[tb,n]*W2[j,n] + b2[j]
// 256 threads, 256 tb-rows per CTA (halves W2 smem-fill amortized traffic
// and CTA count). Per-row accumulation order unchanged -> bit-identical cur2.
// ---------------------------------------------------------------------------
__global__ __launch_bounds__(256) void k_gemm2(const float* __restrict__ W2,
                                               const float* __restrict__ b2) {
    __shared__ float         w2s[NO * NH];        // 40960 B
    __shared__ unsigned char sp[256 * 36];        // 256 rows, 32B + 4B pad

    int tid = threadIdx.x;
    int tb0 = blockIdx.x * 256;

    const float4* w2g = (const float4*)W2;
    float4* w2s4 = (float4*)w2s;
#pragma unroll
    for (int i = tid; i < (NO * NH) / 4; i += 256) w2s4[i] = w2g[i];

    float acc[NO];
#pragma unroll
    for (int j = 0; j < NO; j++) acc[j] = 0.0f;

    for (int kc = 0; kc < NH / 32; kc++) {   // 32 chunks of 32 n
        __syncthreads();
        // load 256 rows x 32 bytes of spikes -> smem (padded stride 36)
#pragma unroll
        for (int i = 0; i < 8; i++) {
            int lin = i * 256 + tid;       // 0..2047 uint32 slots
            int r = lin >> 3;              // 0..255
            int c = lin & 7;               // 0..7
            uint32_t v = *(const uint32_t*)(g_spk1 + (size_t)(tb0 + r) * NH + kc * 32 + c * 4);
            *(uint32_t*)(sp + r * 36 + c * 4) = v;
        }
        __syncthreads();

        const uint32_t* myrow = (const uint32_t*)(sp + tid * 36);
#pragma unroll
        for (int q = 0; q < 8; q++) {
            uint32_t v = myrow[q];
            float s0 = (float)(v & 1u);
            float s1 = (float)((v >> 8) & 1u);
            float s2 = (float)((v >> 16) & 1u);
            float s3 = (float)((v >> 24) & 1u);
            int fidx = kc * 8 + q;
#pragma unroll
            for (int j = 0; j < NO; j++) {
                float4 w = ((const float4*)(w2s + j * NH))[fidx];
                acc[j] += s0 * w.x;
                acc[j] += s1 * w.y;
                acc[j] += s2 * w.z;
                acc[j] += s3 * w.w;
            }
        }
    }

#pragma unroll
    for (int j = 0; j < NO; j++)
        g_cur2[(size_t)(tb0 + tid) * NO + j] = acc[j] + __ldg(&b2[j]);
}

// ---------------------------------------------------------------------------
// Kernel D: layer-2 leaky scan; writes spk2_rec then final mem2.
// ---------------------------------------------------------------------------
__global__ __launch_bounds__(256) void k_scan2(float* __restrict__ out) {
    __shared__ float sc[25][256];
    int idx = blockIdx.x * 256 + threadIdx.x;   // 0 .. B*NO-1 (5120)
    const int stride = BATCH * NO;
    float m = 0.0f;
    for (int tc = 0; tc < 4; tc++) {
        __syncthreads();
#pragma unroll
        for (int j = 0; j < 25; j++)
            sc[j][threadIdx.x] = g_cur2[(size_t)(tc * 25 + j) * stride + idx];
        __syncthreads();
#pragma unroll
        for (int j = 0; j < 25; j++) {
            int t = tc * 25 + j;
            float c = sc[j][threadIdx.x];
            float reset = (m > 1.0f) ? 1.0f : 0.0f;
            m = 0.9f * m + c - reset;
            out[(size_t)t * stride + idx] = (m > 1.0f) ? 1.0f : 0.0f;
        }
    }
    out[(size_t)T_STEPS * stride + idx] = m;   // final mem2
}

// ---------------------------------------------------------------------------
extern "C" void kernel_launch(void* const* d_in, const int* in_sizes, int n_in,
                              void* d_out, int out_size) {
    const float* x  = (const float*)d_in[0];   // [T,B,NI]
    const float* W1 = (const float*)d_in[1];   // [NH,NI]
    const float* b1 = (const float*)d_in[2];   // [NH]
    const float* W2 = (const float*)d_in[3];   // [NO,NH]
    const float* b2 = (const float*)d_in[4];   // [NO]
    float* out = (float*)d_out;

    // A: big GEMM cur1 = x @ W1^T + b1 (double-buffered smem, R11 config)
    dim3 gridA(NH / 128, M_TOT / 128);         // (8, 400)
    k_gemm1<<<gridA, 256>>>(x, W1, b1);

    // B: layer-1 scan -> spikes (4 neurons/thread)
    k_scan1<<<(BATCH * NH / 4) / 256, 256>>>();

    // C: cur2 = spk1 @ W2^T + b2 (256 rows/CTA)
    k_gemm2<<<M_TOT / 256, 256>>>(W2, b2);

    // D: layer-2 scan -> output spikes + final mem2
    k_scan2<<<(BATCH * NO) / 256, 256>>>(out);
}

// round 14
// speedup vs baseline: 1.0270x; 1.0270x over previous
#include <cuda_runtime.h>
#include <stdint.h>

// Problem dims
#define T_STEPS 100
#define BATCH   512
#define NI      784
#define NH      1024
#define NO      10
#define M_TOT   (T_STEPS * BATCH)   // 51200
#define NIT     49                   // K chunks of 16

// Scratch (static __device__ arrays: allocation-free per harness rules)
__device__ float          g_cur1[(size_t)M_TOT * NH];   // ~210 MB
__device__ unsigned char  g_spk1[(size_t)M_TOT * NH];   // ~52 MB
__device__ float          g_cur2[(size_t)M_TOT * NO];   // ~2 MB

// ---------------------------------------------------------------------------
// Kernel A: cur1[m,n] = sum_k X[m,k]*W1[n,k] + b1[n]
// R11-proven config: 128x128x16 SGEMM, 256 thr, 8x8 microtile, smem
// double-buffered (one __syncthreads per K-iter), plain fragment loads.
// cur1 stored with .cs (streaming, evict-first: single-use 210MB stream).
// Accumulation order identical to round 1 -> bit-identical cur1.
// ---------------------------------------------------------------------------
__global__ __launch_bounds__(256, 2) void k_gemm1(const float* __restrict__ X,
                                                  const float* __restrict__ W1,
                                                  const float* __restrict__ bias) {
    __shared__ __align__(16) float As[2][16][128];
    __shared__ __align__(16) float Bs[2][16][128];
    const int K = NI;       // 784 = 49 * 16
    const int N = NH;       // 1024

    int tid = threadIdx.x;
    int bn  = blockIdx.x;   // 0..7
    int bm  = blockIdx.y;   // 0..399

    int lrow = tid >> 1;          // 0..127
    int lcol = (tid & 1) << 3;    // 0 or 8

    const float* aptr = X  + (size_t)(bm * 128 + lrow) * K + lcol;
    const float* bptr = W1 + (size_t)(bn * 128 + lrow) * K + lcol;

    int ty = tid >> 4;   // 0..15
    int tx = tid & 15;   // 0..15

    float acc[8][8];
#pragma unroll
    for (int i = 0; i < 8; i++)
#pragma unroll
        for (int j = 0; j < 8; j++) acc[i][j] = 0.0f;

    float4 a0, a1, b0, b1;

    // ---- prologue: tile 0 -> regs -> buf 0 ----
    a0 = *(const float4*)(aptr);
    a1 = *(const float4*)(aptr + 4);
    b0 = *(const float4*)(bptr);
    b1 = *(const float4*)(bptr + 4);
    As[0][lcol + 0][lrow] = a0.x; As[0][lcol + 1][lrow] = a0.y;
    As[0][lcol + 2][lrow] = a0.z; As[0][lcol + 3][lrow] = a0.w;
    As[0][lcol + 4][lrow] = a1.x; As[0][lcol + 5][lrow] = a1.y;
    As[0][lcol + 6][lrow] = a1.z; As[0][lcol + 7][lrow] = a1.w;
    Bs[0][lcol + 0][lrow] = b0.x; Bs[0][lcol + 1][lrow] = b0.y;
    Bs[0][lcol + 2][lrow] = b0.z; Bs[0][lcol + 3][lrow] = b0.w;
    Bs[0][lcol + 4][lrow] = b1.x; Bs[0][lcol + 5][lrow] = b1.y;
    Bs[0][lcol + 6][lrow] = b1.z; Bs[0][lcol + 7][lrow] = b1.w;
    // prefetch tile 1 into regs
    a0 = *(const float4*)(aptr + 16);
    a1 = *(const float4*)(aptr + 20);
    b0 = *(const float4*)(bptr + 16);
    b1 = *(const float4*)(bptr + 20);
    __syncthreads();

    for (int it = 0; it < NIT; it++) {
        const int buf = it & 1;
        const int nbuf = buf ^ 1;

        // ---- STS tile(it+1) into the other buffer ----
        if (it + 1 < NIT) {
            As[nbuf][lcol + 0][lrow] = a0.x; As[nbuf][lcol + 1][lrow] = a0.y;
            As[nbuf][lcol + 2][lrow] = a0.z; As[nbuf][lcol + 3][lrow] = a0.w;
            As[nbuf][lcol + 4][lrow] = a1.x; As[nbuf][lcol + 5][lrow] = a1.y;
            As[nbuf][lcol + 6][lrow] = a1.z; As[nbuf][lcol + 7][lrow] = a1.w;
            Bs[nbuf][lcol + 0][lrow] = b0.x; Bs[nbuf][lcol + 1][lrow] = b0.y;
            Bs[nbuf][lcol + 2][lrow] = b0.z; Bs[nbuf][lcol + 3][lrow] = b0.w;
            Bs[nbuf][lcol + 4][lrow] = b1.x; Bs[nbuf][lcol + 5][lrow] = b1.y;
            Bs[nbuf][lcol + 6][lrow] = b1.z; Bs[nbuf][lcol + 7][lrow] = b1.w;
        }
        // ---- LDG prefetch tile(it+2) (latency hidden under compute) ----
        if (it + 2 < NIT) {
            const int kf = (it + 2) * 16;
            a0 = *(const float4*)(aptr + kf);
            a1 = *(const float4*)(aptr + kf + 4);
            b0 = *(const float4*)(bptr + kf);
            b1 = *(const float4*)(bptr + kf + 4);
        }

        // ---- compute from current buffer (identical order to round 1) ----
#pragma unroll
        for (int kk = 0; kk < 16; kk++) {
            float4 aA = *(const float4*)&As[buf][kk][ty * 4];
            float4 aB = *(const float4*)&As[buf][kk][ty * 4 + 64];
            float4 bA = *(const float4*)&Bs[buf][kk][tx * 4];
            float4 bB = *(const float4*)&Bs[buf][kk][tx * 4 + 64];
            float av[8] = {aA.x, aA.y, aA.z, aA.w, aB.x, aB.y, aB.z, aB.w};
            float bv[8] = {bA.x, bA.y, bA.z, bA.w, bB.x, bB.y, bB.z, bB.w};
#pragma unroll
            for (int i = 0; i < 8; i++)
#pragma unroll
                for (int j = 0; j < 8; j++)
                    acc[i][j] += av[i] * bv[j];
        }
        __syncthreads();
    }

    // Epilogue (streaming stores: cur1 is read exactly once, by k_scan1)
    int crow0 = bm * 128 + ty * 4;
    int ccol0 = bn * 128 + tx * 4;
    float4 bs0 = *(const float4*)(bias + ccol0);
    float4 bs1 = *(const float4*)(bias + ccol0 + 64);

#pragma unroll
    for (int i = 0; i < 4; i++) {
        float* c0 = g_cur1 + (size_t)(crow0 + i) * N + ccol0;
        float4 v;
        v.x = acc[i][0] + bs0.x; v.y = acc[i][1] + bs0.y;
        v.z = acc[i][2] + bs0.z; v.w = acc[i][3] + bs0.w;
        __stcs((float4*)(c0), v);
        v.x = acc[i][4] + bs1.x; v.y = acc[i][5] + bs1.y;
        v.z = acc[i][6] + bs1.z; v.w = acc[i][7] + bs1.w;
        __stcs((float4*)(c0 + 64), v);

        float* c1 = g_cur1 + (size_t)(crow0 + 64 + i) * N + ccol0;
        v.x = acc[4 + i][0] + bs0.x; v.y = acc[4 + i][1] + bs0.y;
        v.z = acc[4 + i][2] + bs0.z; v.w = acc[4 + i][3] + bs0.w;
        __stcs((float4*)(c1), v);
        v.x = acc[4 + i][4] + bs1.x; v.y = acc[4 + i][5] + bs1.y;
        v.z = acc[4 + i][6] + bs1.z; v.w = acc[4 + i][7] + bs1.w;
        __stcs((float4*)(c1 + 64), v);
    }
}

// ---------------------------------------------------------------------------
// Kernel B: layer-1 leaky scan, 4 neurons per thread (float4/uchar4) with
// explicit one-iteration register prefetch (loads are address-independent of
// the membrane chain) and evict-first loads. Math order unchanged.
// ---------------------------------------------------------------------------
__global__ __launch_bounds__(256) void k_scan1() {
    int i4 = blockIdx.x * blockDim.x + threadIdx.x;   // 0 .. B*NH/4-1
    const size_t stride = (size_t)BATCH * NH;
    const float4* base = (const float4*)g_cur1 + i4;
    const size_t stride4 = stride >> 2;   // float4 stride per t

    float m0 = 0.0f, m1 = 0.0f, m2 = 0.0f, m3 = 0.0f;
    float4 cur = __ldcs(base);
    for (int t = 0; t < T_STEPS; t++) {
        float4 nxt;
        if (t + 1 < T_STEPS) nxt = __ldcs(base + (size_t)(t + 1) * stride4);
        m0 = 0.9f * m0 + cur.x - ((m0 > 1.0f) ? 1.0f : 0.0f);
        m1 = 0.9f * m1 + cur.y - ((m1 > 1.0f) ? 1.0f : 0.0f);
        m2 = 0.9f * m2 + cur.z - ((m2 > 1.0f) ? 1.0f : 0.0f);
        m3 = 0.9f * m3 + cur.w - ((m3 > 1.0f) ? 1.0f : 0.0f);
        uchar4 s;
        s.x = (m0 > 1.0f) ? 1 : 0;
        s.y = (m1 > 1.0f) ? 1 : 0;
        s.z = (m2 > 1.0f) ? 1 : 0;
        s.w = (m3 > 1.0f) ? 1 : 0;
        *(uchar4*)(g_spk1 + (size_t)t * stride + (size_t)i4 * 4) = s;
        cur = nxt;
    }
}

// ---------------------------------------------------------------------------
// Kernel C: cur2[tb,j] = sum_n spk1[tb,n]*W2[j,n] + b2[j]  (R11 config)
// ---------------------------------------------------------------------------
__global__ __launch_bounds__(128) void k_gemm2(const float* __restrict__ W2,
                                               const float* __restrict__ b2) {
    __shared__ float         w2s[NO * NH];        // 40960 B
    __shared__ unsigned char sp[128 * 36];        // 128 rows, 32B + 4B pad

    int tid = threadIdx.x;
    int tb0 = blockIdx.x * 128;

    const float4* w2g = (const float4*)W2;
    float4* w2s4 = (float4*)w2s;
#pragma unroll
    for (int i = tid; i < (NO * NH) / 4; i += 128) w2s4[i] = w2g[i];

    float acc[NO];
#pragma unroll
    for (int j = 0; j < NO; j++) acc[j] = 0.0f;

    for (int kc = 0; kc < NH / 32; kc++) {   // 32 chunks of 32 n
        __syncthreads();
#pragma unroll
        for (int i = 0; i < 8; i++) {
            int lin = i * 128 + tid;
            int r = lin >> 3;
            int c = lin & 7;
            uint32_t v = *(const uint32_t*)(g_spk1 + (size_t)(tb0 + r) * NH + kc * 32 + c * 4);
            *(uint32_t*)(sp + r * 36 + c * 4) = v;
        }
        __syncthreads();

        const uint32_t* myrow = (const uint32_t*)(sp + tid * 36);
#pragma unroll
        for (int q = 0; q < 8; q++) {
            uint32_t v = myrow[q];
            float s0 = (float)(v & 1u);
            float s1 = (float)((v >> 8) & 1u);
            float s2 = (float)((v >> 16) & 1u);
            float s3 = (float)((v >> 24) & 1u);
            int fidx = kc * 8 + q;
#pragma unroll
            for (int j = 0; j < NO; j++) {
                float4 w = ((const float4*)(w2s + j * NH))[fidx];
                acc[j] += s0 * w.x;
                acc[j] += s1 * w.y;
                acc[j] += s2 * w.z;
                acc[j] += s3 * w.w;
            }
        }
    }

#pragma unroll
    for (int j = 0; j < NO; j++)
        g_cur2[(size_t)(tb0 + tid) * NO + j] = acc[j] + __ldg(&b2[j]);
}

// ---------------------------------------------------------------------------
// Kernel D: layer-2 leaky scan; writes spk2_rec then final mem2.
// ---------------------------------------------------------------------------
__global__ __launch_bounds__(256) void k_scan2(float* __restrict__ out) {
    __shared__ float sc[25][256];
    int idx = blockIdx.x * 256 + threadIdx.x;   // 0 .. B*NO-1 (5120)
    const int stride = BATCH * NO;
    float m = 0.0f;
    for (int tc = 0; tc < 4; tc++) {
        __syncthreads();
#pragma unroll
        for (int j = 0; j < 25; j++)
            sc[j][threadIdx.x] = g_cur2[(size_t)(tc * 25 + j) * stride + idx];
        __syncthreads();
#pragma unroll
        for (int j = 0; j < 25; j++) {
            int t = tc * 25 + j;
            float c = sc[j][threadIdx.x];
            float reset = (m > 1.0f) ? 1.0f : 0.0f;
            m = 0.9f * m + c - reset;
            out[(size_t)t * stride + idx] = (m > 1.0f) ? 1.0f : 0.0f;
        }
    }
    out[(size_t)T_STEPS * stride + idx] = m;   // final mem2
}

// ---------------------------------------------------------------------------
extern "C" void kernel_launch(void* const* d_in, const int* in_sizes, int n_in,
                              void* d_out, int out_size) {
    const float* x  = (const float*)d_in[0];   // [T,B,NI]
    const float* W1 = (const float*)d_in[1];   // [NH,NI]
    const float* b1 = (const float*)d_in[2];   // [NH]
    const float* W2 = (const float*)d_in[3];   // [NO,NH]
    const float* b2 = (const float*)d_in[4];   // [NO]
    float* out = (float*)d_out;

    // A: big GEMM cur1 = x @ W1^T + b1 (R11 config + streaming stores)
    dim3 gridA(NH / 128, M_TOT / 128);         // (8, 400)
    k_gemm1<<<gridA, 256>>>(x, W1, b1);

    // B: layer-1 scan -> spikes (4 neurons/thread, prefetched)
    k_scan1<<<(BATCH * NH / 4) / 256, 256>>>();

    // C: cur2 = spk1 @ W2^T + b2 (R11 128-thread config)
    k_gemm2<<<M_TOT / 128, 128>>>(W2, b2);

    // D: layer-2 scan -> output spikes + final mem2
    k_scan2<<<(BATCH * NO) / 256, 256>>>(out);
}